// round 1
// baseline (speedup 1.0000x reference)
#include <cuda_runtime.h>

// out[i, h=n*7+o, m] = sum_{j<48,k<3} W[i,j,k] * x[j, n*7+(o+k-1), m]
//   (term dropped when o+k-1 outside [0,7))
// x: (48,56,56) f32   W: (192,48,3) f32   out: (192,56,56) f32

#define JCH 48
#define KTAP 3
#define MW 56
#define MP 64          // padded m (float4-friendly)
#define BI 64          // output channels per block
#define NTHREADS 128

__global__ __launch_bounds__(NTHREADS)
void fold_conv_kernel(const float* __restrict__ x,
                      const float* __restrict__ W,
                      float* __restrict__ out)
{
    extern __shared__ float sm[];
    float* xs = sm;                      // [KTAP][JCH][MP] = 3*48*64
    float* ws = sm + KTAP * JCH * MP;    // [JCH*KTAP][BI]  = 144*64

    const int tid = threadIdx.x;
    const int h  = blockIdx.x;           // 0..55
    const int n  = h / 7;
    const int o  = h - n * 7;
    const int i0 = blockIdx.y * BI;      // 0,64,128

    // ---- load x slab (3 taps x 48 ch x 56 m, zero-padded) ----
    for (int idx = tid; idx < KTAP * JCH * MP; idx += NTHREADS) {
        int k   = idx / (JCH * MP);
        int rem = idx - k * (JCH * MP);
        int j   = rem >> 6;              // / MP
        int m   = rem & (MP - 1);
        int r   = o + k - 1;
        float v = 0.0f;
        if (r >= 0 && r < 7 && m < MW)
            v = x[(j * 56 + n * 7 + r) * 56 + m];
        xs[idx] = v;
    }
    // ---- load W tile, transposed to [jk][ii] so i is vector-contiguous ----
    for (int idx = tid; idx < JCH * KTAP * BI; idx += NTHREADS) {
        int ii = idx & (BI - 1);
        int jk = idx >> 6;               // j*3+k, matches W row layout
        ws[idx] = W[(i0 + ii) * (JCH * KTAP) + jk];
    }
    __syncthreads();

    // ---- register-tiled mainloop: each thread computes 4i x 8m ----
    const int ig  = tid & 15;            // 16 i-groups
    const int mg  = tid >> 4;            // 8 m-groups (mg==7 covers padding, discarded)
    const int ii0 = ig * 4;
    const int m0  = mg * 8;

    float acc[4][8];
    #pragma unroll
    for (int a = 0; a < 4; ++a)
        #pragma unroll
        for (int b = 0; b < 8; ++b)
            acc[a][b] = 0.0f;

    #pragma unroll 1
    for (int j = 0; j < JCH; ++j) {
        #pragma unroll
        for (int k = 0; k < KTAP; ++k) {
            const float4 wv = *(const float4*)&ws[(j * 3 + k) * BI + ii0];
            const float4 xa = *(const float4*)&xs[(k * JCH + j) * MP + m0];
            const float4 xb = *(const float4*)&xs[(k * JCH + j) * MP + m0 + 4];
            const float wr[4] = {wv.x, wv.y, wv.z, wv.w};
            const float xr[8] = {xa.x, xa.y, xa.z, xa.w, xb.x, xb.y, xb.z, xb.w};
            #pragma unroll
            for (int a = 0; a < 4; ++a)
                #pragma unroll
                for (int b = 0; b < 8; ++b)
                    acc[a][b] = fmaf(wr[a], xr[b], acc[a][b]);
        }
    }

    // ---- store (skip padded m-group; offsets are 32B-aligned -> float4 OK) ----
    if (m0 < MW) {
        #pragma unroll
        for (int a = 0; a < 4; ++a) {
            const int i = i0 + ii0 + a;
            float* op = &out[(i * 56 + h) * 56 + m0];
            float4 v0 = {acc[a][0], acc[a][1], acc[a][2], acc[a][3]};
            float4 v1 = {acc[a][4], acc[a][5], acc[a][6], acc[a][7]};
            *(float4*)(op)     = v0;
            *(float4*)(op + 4) = v1;
        }
    }
}

extern "C" void kernel_launch(void* const* d_in, const int* in_sizes, int n_in,
                              void* d_out, int out_size)
{
    const float* x = (const float*)d_in[0];   // 48*56*56
    const float* W = (const float*)d_in[1];   // 192*48*3
    float* out = (float*)d_out;               // 192*56*56

    const int smem = (KTAP * JCH * MP + JCH * KTAP * BI) * (int)sizeof(float); // 73728 B
    static bool attr_set = false;
    if (!attr_set) {
        cudaFuncSetAttribute(fold_conv_kernel,
                             cudaFuncAttributeMaxDynamicSharedMemorySize, smem);
        attr_set = true;
    }
    dim3 grid(56, 3);
    fold_conv_kernel<<<grid, NTHREADS, smem>>>(x, W, out);
}

// round 2
// speedup vs baseline: 1.9238x; 1.9238x over previous
#include <cuda_runtime.h>

// out[i, h=n*7+o, m] = sum_{j<48,k<3} W[i,j,k] * x[j, n*7+(o+k-1), m]
//   (term dropped when o+k-1 outside [0,7))
// x: (48,56,56) f32   W: (192,48,3) f32   out: (192,56,56) f32

#define JCH 48
#define KTAP 3
#define MW 56
#define MP 64            // padded m (float4-friendly)
#define BI 32            // output channels per block
#define WS_STRIDE 148    // 148%4==0 (aligned f4) and 4*148 % 32 == 16 (ig rows on distinct banks)
#define NTHREADS 128

__global__ __launch_bounds__(NTHREADS)
void fold_conv_kernel(const float* __restrict__ x,
                      const float* __restrict__ W,
                      float* __restrict__ out)
{
    extern __shared__ float sm[];
    float* xs = sm;                         // [KTAP*JCH][MP]   = 144*64 floats
    float* ws = sm + KTAP * JCH * MP;       // [BI][WS_STRIDE]  = 32*148 floats

    const int tid = threadIdx.x;
    const int h  = blockIdx.x;              // 0..55
    const int n  = h / 7;
    const int o  = h - n * 7;
    const int i0 = blockIdx.y * BI;         // 0..160 step 32

    // ---- load x slab: 144 rows x 16 float4, coalesced, zero-padded ----
    {
        float4* xs4 = (float4*)xs;
        #pragma unroll
        for (int it = 0; it < (KTAP * JCH * 16) / NTHREADS; ++it) {
            int idx = tid + it * NTHREADS;          // 0..2303
            int row = idx >> 4;                     // k*48+j
            int s   = idx & 15;                     // float4 slot
            int k   = row / JCH;
            int j   = row - k * JCH;
            int r   = o + k - 1;
            float4 v = make_float4(0.f, 0.f, 0.f, 0.f);
            if (r >= 0 && r < 7 && s < 14)
                v = *(const float4*)&x[(j * 56 + n * 7 + r) * 56 + s * 4];
            xs4[idx] = v;
        }
    }
    // ---- load W tile: coalesced f4 gmem read, aligned f4 smem write ----
    #pragma unroll
    for (int it = 0; it < (BI * 36) / NTHREADS; ++it) {
        int idx = tid + it * NTHREADS;              // 0..1151
        int ii  = idx / 36;
        int q   = idx - ii * 36;                    // f4 slot within 144
        float4 v = *(const float4*)&W[(i0 + ii) * (JCH * KTAP) + q * 4];
        *(float4*)&ws[ii * WS_STRIDE + q * 4] = v;
    }
    __syncthreads();

    // ---- register-tiled mainloop: each thread computes 4i x 4m ----
    const int mg  = tid & 15;               // m fastest -> coalesced stores
    const int ig  = tid >> 4;               // 8 i-groups
    const int m0  = mg * 4;                 // mg 14,15 are padding (discarded)
    const int ii0 = ig * 4;

    float acc[4][4];
    #pragma unroll
    for (int a = 0; a < 4; ++a)
        #pragma unroll
        for (int b = 0; b < 4; ++b)
            acc[a][b] = 0.0f;

    const float* wbase = ws + ii0 * WS_STRIDE;

    #pragma unroll 4
    for (int j = 0; j < JCH; ++j) {
        float4 xv[KTAP];
        #pragma unroll
        for (int k = 0; k < KTAP; ++k)
            xv[k] = *(const float4*)&xs[(k * JCH + j) * MP + m0];
        #pragma unroll
        for (int a = 0; a < 4; ++a) {
            #pragma unroll
            for (int k = 0; k < KTAP; ++k) {
                const float w = wbase[a * WS_STRIDE + j * 3 + k];
                acc[a][0] = fmaf(w, xv[k].x, acc[a][0]);
                acc[a][1] = fmaf(w, xv[k].y, acc[a][1]);
                acc[a][2] = fmaf(w, xv[k].z, acc[a][2]);
                acc[a][3] = fmaf(w, xv[k].w, acc[a][3]);
            }
        }
    }

    // ---- store (skip padded m-groups; 16B-aligned float4) ----
    if (m0 < MW) {
        #pragma unroll
        for (int a = 0; a < 4; ++a) {
            const int i = i0 + ii0 + a;
            float4 v = {acc[a][0], acc[a][1], acc[a][2], acc[a][3]};
            *(float4*)&out[(i * 56 + h) * 56 + m0] = v;
        }
    }
}

extern "C" void kernel_launch(void* const* d_in, const int* in_sizes, int n_in,
                              void* d_out, int out_size)
{
    const float* x = (const float*)d_in[0];   // 48*56*56
    const float* W = (const float*)d_in[1];   // 192*48*3
    float* out = (float*)d_out;               // 192*56*56

    const int smem = (KTAP * JCH * MP + BI * WS_STRIDE) * (int)sizeof(float); // 55808 B
    static bool attr_set = false;
    if (!attr_set) {
        cudaFuncSetAttribute(fold_conv_kernel,
                             cudaFuncAttributeMaxDynamicSharedMemorySize, smem);
        attr_set = true;
    }
    dim3 grid(56, 6);
    fold_conv_kernel<<<grid, NTHREADS, smem>>>(x, W, out);
}